// round 11
// baseline (speedup 1.0000x reference)
#include <cuda_runtime.h>

#define GN    6
#define NN    36
#define NB7   7            // 7x7 counter grid incl. trash row/col
#define NPED  8192
#define HID   128
#define RPB   128          // rows per count block (proven 28 warps/SM config)
#define NSL   16           // j-slices
#define JCH   (NPED / NSL) // 512
#define HB4   (NPED / 4)   // 2048 u32 words per (slice,bin): 4 byte-packed rows/word

// Per-slice byte-packed partial counts: g8[((sl*NN)+c)*HB4 + i/4], byte q = row i%4.
// Fully overwritten by count_kernel every launch -> no zeroing, replay-safe.
__device__ unsigned g8[NSL * NN * HB4];   // 4.7 MB

// W transposed: viewed as float[c][h] (h contiguous). Written by count block
// (0,0) every launch; read by embed (runs after count completes).
__device__ float2 g_WT2[NN * (HID / 2)];

// ---------------------------------------------------------------------------
// Phase 1: branch-free occupancy histogram, conflict-free u32 counters.
// (hot loop byte-identical to R8/R10: measured 34.9us, at its issue-slot
// floor). Block (0,0) additionally transposes W into g_WT2 — 36 elements
// per thread, hidden under the other 1023 blocks' work.
// ---------------------------------------------------------------------------
__global__ __launch_bounds__(RPB) void count_kernel(const float* __restrict__ obs2,
                                                    const float* __restrict__ W) {
    __shared__ unsigned   cnt[NB7 * NB7 * RPB];  // [bin49][t], bank = t%32 (conflict-free)
    __shared__ ulonglong2 pts[JCH / 2];          // 4 KB

    const int t  = threadIdx.x;
    const int i  = blockIdx.x * RPB + t;
    const int j0 = blockIdx.y * JCH;

    // Fold the W transpose into one block (coalesced reads, scattered writes).
    if (blockIdx.x == 0 && blockIdx.y == 0) {
        float* WT = (float*)g_WT2;
#pragma unroll
        for (int k = 0; k < HID * NN / RPB; k++) {
            const int idx = k * RPB + t;
            const int h = idx / NN;
            const int c = idx - h * NN;
            WT[c * HID + h] = W[idx];
        }
    }

    {
        const ulonglong2* src = (const ulonglong2*)(obs2 + 2 * j0);
#pragma unroll
        for (int k = 0; k < JCH / 2 / RPB; k++)
            pts[t + k * RPB] = src[t + k * RPB];
    }
#pragma unroll
    for (int k = 0; k < NB7 * NB7; k++)
        cnt[k * RPB + t] = 0u;

    const float2 pi = ((const float2*)obs2)[i];
    float nx = -pi.x, ny = -pi.y;
    unsigned long long negpi;
    asm("mov.b64 %0, {%1,%2};" : "=l"(negpi) : "f"(nx), "f"(ny));
    const unsigned long long THREE2 = 0x4040000040400000ULL;  // (3.0f, 3.0f)
    const float MAGIC = 8388608.0f;                           // 2^23

    __syncthreads();

    unsigned* mycnt = cnt + t;

#pragma unroll 4
    for (int k = 0; k < JCH / 2; k++) {
        const ulonglong2 pp = pts[k];   // LDS.128 broadcast: two points
#pragma unroll
        for (int half = 0; half < 2; half++) {
            const unsigned long long pj = half ? pp.y : pp.x;
            unsigned long long d, e;
            // EXACT reference order per lane: rn(pj - pi), then rn(+3)
            asm("add.rn.f32x2 %0, %1, %2;" : "=l"(d) : "l"(pj), "l"(negpi));
            asm("add.rn.f32x2 %0, %1, %2;" : "=l"(e) : "l"(d), "l"(THREE2));
            const float ex = __uint_as_float((unsigned)e);
            const float ey = __uint_as_float((unsigned)(e >> 32));
            float fx, fy;
            asm("add.rm.f32 %0, %1, %2;" : "=f"(fx) : "f"(ex), "f"(MAGIC));
            asm("add.rm.f32 %0, %1, %2;" : "=f"(fy) : "f"(ey), "f"(MAGIC));
            unsigned bx = __float_as_uint(fx) - 0x4B000000u;  // floor; OOR -> huge
            unsigned by = __float_as_uint(fy) - 0x4B000000u;
            bx = umin(bx, 6u);
            by = umin(by, 6u);
            mycnt[(bx * NB7 + by) * RPB] += 1u;  // conflict-free RMW, no branch
        }
    }

    __syncthreads();

    // Flush 36 valid bins, byte-packed 4 rows/word (per-slice counts < 255).
    const int sl = blockIdx.y;
#pragma unroll
    for (int k = 0; k < 9; k++) {
        const int gidx = k * RPB + t;     // 0..1151
        const int vb   = gidx >> 5;
        const int w    = gidx & 31;
        const int b49  = (vb / GN) * NB7 + (vb % GN);
        const unsigned b0 = cnt[b49 * RPB + 4 * w + 0];
        const unsigned b1 = cnt[b49 * RPB + 4 * w + 1];
        const unsigned b2 = cnt[b49 * RPB + 4 * w + 2];
        const unsigned b3 = cnt[b49 * RPB + 4 * w + 3];
        g8[(sl * NN + vb) * HB4 + blockIdx.x * (RPB / 4) + w] =
            b0 | (b1 << 8) | (b2 << 16) | (b3 << 24);
    }
}

// ---------------------------------------------------------------------------
// Phase 2: reduce slices, remove self pair (always bin 21), register-blocked
// GEMM (2 h per thread via COALESCED float2 loads from transposed W).
// 1024 blocks x 128 thr, block = 8 rows x 128 h. (byte-identical to R10)
// ---------------------------------------------------------------------------
__global__ __launch_bounds__(HID) void embed_kernel(const float* __restrict__ b,
                                                    float* __restrict__ out) {
    __shared__ float cs[8][NN];   // reduced counts for this block's 8 rows

    const int t  = threadIdx.x;
    const int i0 = blockIdx.x * 8;

    // Phase A: 36 bins x 2 words (4 rows each) = 72 tasks; 16 independent
    // u32 loads per task (high MLP), packed-u16 accumulation (max 960).
    if (t < NN * 2) {
        const int c    = t >> 1;
        const int half = t & 1;           // rows half*4 .. half*4+3
        const unsigned* gp = g8 + c * HB4 + (i0 >> 2) + half;
        unsigned a01 = 0u, a23 = 0u;
#pragma unroll
        for (int sl = 0; sl < NSL; sl++) {
            const unsigned v = gp[sl * NN * HB4];
            a01 += __byte_perm(v, 0, 0x4140);   // (b0,b1) as u16 pair
            a23 += __byte_perm(v, 0, 0x4342);   // (b2,b3)
        }
        const unsigned self = (c == 3 * GN + 3) ? 1u : 0u;
        const int r0 = half * 4;
        cs[r0 + 0][c] = (float)((a01 & 0xFFFFu) - self);
        cs[r0 + 1][c] = (float)((a01 >> 16)     - self);
        cs[r0 + 2][c] = (float)((a23 & 0xFFFFu) - self);
        cs[r0 + 3][c] = (float)((a23 >> 16)     - self);
    }
    __syncthreads();

    // Phase B: h0 = 2*(t%64), rows (t/64)*4 .. +3.
    // w loads: lanes consecutive in h-pair index -> coalesced LDG.64,
    // 18KB WT is L1-resident after warmup.
    const int hp = t & 63;          // h pair index, h0 = 2*hp
    const int rg = t >> 6;

    float w[2 * NN];
#pragma unroll
    for (int c = 0; c < NN; c++) {
        const float2 p = g_WT2[c * (HID / 2) + hp];
        w[c]      = p.x;
        w[NN + c] = p.y;
    }
    const float2 bh = ((const float2*)b)[hp];

#pragma unroll
    for (int r = 0; r < 4; r++) {
        const int row = rg * 4 + r;
        float a0 = bh.x, a1 = bh.y;
#pragma unroll
        for (int c = 0; c < NN; c++) {
            const float v = cs[row][c];        // broadcast LDS -> 2 FMAs
            a0 = fmaf(v, w[c], a0);
            a1 = fmaf(v, w[NN + c], a1);
        }
        *(float2*)&out[(i0 + row) * HID + 2 * hp] = make_float2(a0, a1);
    }
}

// ---------------------------------------------------------------------------
// Inputs: 0 hidden_state (unused), 1 obs1 (unused), 2 obs2 [8192,2],
// 3 W [128,36], 4 b [128]. Output fp32 [8192,128].
// ---------------------------------------------------------------------------
extern "C" void kernel_launch(void* const* d_in, const int* in_sizes, int n_in,
                              void* d_out, int out_size) {
    const float* obs2 = (const float*)d_in[2];
    const float* W    = (const float*)d_in[3];
    const float* b    = (const float*)d_in[4];
    float*       out  = (float*)d_out;

    dim3 g1(NPED / RPB, NSL);        // 64 x 16 = 1024 blocks
    count_kernel<<<g1, RPB>>>(obs2, W);
    embed_kernel<<<NPED / 8, HID>>>(b, out);
}

// round 12
// speedup vs baseline: 1.0972x; 1.0972x over previous
#include <cuda_runtime.h>

#define GN    6
#define NN    36
#define NB7   7            // 7x7 counter grid incl. trash row/col
#define NPED  8192
#define HID   128
#define RPB   128          // rows per count block (proven 28 warps/SM config)
#define NSL   16           // j-slices
#define JCH   (NPED / NSL) // 512
#define HB4   (NPED / 4)   // 2048 u32 words per (slice,bin): 4 byte-packed rows/word

// Per-slice byte-packed partial counts: g8[((sl*NN)+c)*HB4 + i/4], byte q = row i%4.
// Fully overwritten by count_kernel every launch -> no zeroing, replay-safe.
__device__ unsigned g8[NSL * NN * HB4];   // 4.7 MB

// W transposed: WT[c*HID + h] = W[h*NN + c]. Written cooperatively by the 16
// count blocks with blockIdx.x == 0 (disjoint idx ranges); read by embed.
__device__ float g_WT[NN * HID];

// ---------------------------------------------------------------------------
// Phase 1: branch-free occupancy histogram, conflict-free u32 counters.
// Hot loop byte-identical to R8 (measured 34.9us, issue-slot floor).
// Transpose spread over 16 blocks: ~288 scattered stores each (negligible).
// ---------------------------------------------------------------------------
__global__ __launch_bounds__(RPB) void count_kernel(const float* __restrict__ obs2,
                                                    const float* __restrict__ W) {
    __shared__ unsigned   cnt[NB7 * NB7 * RPB];  // [bin49][t], bank = t%32 (conflict-free)
    __shared__ ulonglong2 pts[JCH / 2];          // 4 KB

    const int t  = threadIdx.x;
    const int i  = blockIdx.x * RPB + t;
    const int j0 = blockIdx.y * JCH;

    // Cooperative W transpose: block (0,sl) handles idx [sl*288, (sl+1)*288).
    if (blockIdx.x == 0) {
        const int base = blockIdx.y * (HID * NN / NSL);   // sl*288
        for (int idx = base + t; idx < base + HID * NN / NSL; idx += RPB) {
            const int h = idx / NN;
            const int c = idx - h * NN;
            g_WT[c * HID + h] = W[idx];
        }
    }

    {
        const ulonglong2* src = (const ulonglong2*)(obs2 + 2 * j0);
#pragma unroll
        for (int k = 0; k < JCH / 2 / RPB; k++)
            pts[t + k * RPB] = src[t + k * RPB];
    }
#pragma unroll
    for (int k = 0; k < NB7 * NB7; k++)
        cnt[k * RPB + t] = 0u;

    const float2 pi = ((const float2*)obs2)[i];
    float nx = -pi.x, ny = -pi.y;
    unsigned long long negpi;
    asm("mov.b64 %0, {%1,%2};" : "=l"(negpi) : "f"(nx), "f"(ny));
    const unsigned long long THREE2 = 0x4040000040400000ULL;  // (3.0f, 3.0f)
    const float MAGIC = 8388608.0f;                           // 2^23

    __syncthreads();

    unsigned* mycnt = cnt + t;

#pragma unroll 4
    for (int k = 0; k < JCH / 2; k++) {
        const ulonglong2 pp = pts[k];   // LDS.128 broadcast: two points
#pragma unroll
        for (int half = 0; half < 2; half++) {
            const unsigned long long pj = half ? pp.y : pp.x;
            unsigned long long d, e;
            // EXACT reference order per lane: rn(pj - pi), then rn(+3)
            asm("add.rn.f32x2 %0, %1, %2;" : "=l"(d) : "l"(pj), "l"(negpi));
            asm("add.rn.f32x2 %0, %1, %2;" : "=l"(e) : "l"(d), "l"(THREE2));
            const float ex = __uint_as_float((unsigned)e);
            const float ey = __uint_as_float((unsigned)(e >> 32));
            float fx, fy;
            asm("add.rm.f32 %0, %1, %2;" : "=f"(fx) : "f"(ex), "f"(MAGIC));
            asm("add.rm.f32 %0, %1, %2;" : "=f"(fy) : "f"(ey), "f"(MAGIC));
            unsigned bx = __float_as_uint(fx) - 0x4B000000u;  // floor; OOR -> huge
            unsigned by = __float_as_uint(fy) - 0x4B000000u;
            bx = umin(bx, 6u);
            by = umin(by, 6u);
            mycnt[(bx * NB7 + by) * RPB] += 1u;  // conflict-free RMW, no branch
        }
    }

    __syncthreads();

    // Flush 36 valid bins, byte-packed 4 rows/word (per-slice counts < 255).
    const int sl = blockIdx.y;
#pragma unroll
    for (int k = 0; k < 9; k++) {
        const int gidx = k * RPB + t;     // 0..1151
        const int vb   = gidx >> 5;
        const int w    = gidx & 31;
        const int b49  = (vb / GN) * NB7 + (vb % GN);
        const unsigned b0 = cnt[b49 * RPB + 4 * w + 0];
        const unsigned b1 = cnt[b49 * RPB + 4 * w + 1];
        const unsigned b2 = cnt[b49 * RPB + 4 * w + 2];
        const unsigned b3 = cnt[b49 * RPB + 4 * w + 3];
        g8[(sl * NN + vb) * HB4 + blockIdx.x * (RPB / 4) + w] =
            b0 | (b1 << 8) | (b2 << 16) | (b3 << 24);
    }
}

// ---------------------------------------------------------------------------
// Phase 2: reduce slices, remove self pair (always bin 21), GEMM with ONE h
// per thread (low regs -> high occupancy). w LDGs issued before phase A so
// the two load latencies overlap. 1024 blocks x 128 thr = 8 rows x 128 h.
// ---------------------------------------------------------------------------
__global__ __launch_bounds__(HID) void embed_kernel(const float* __restrict__ b,
                                                    float* __restrict__ out) {
    __shared__ float cs[8][NN];   // reduced counts for this block's 8 rows

    const int t  = threadIdx.x;   // == h
    const int i0 = blockIdx.x * 8;

    // Issue w loads first: lane-consecutive in h -> perfectly coalesced,
    // WT is L1/L2-resident. Latency overlaps phase A below.
    float w[NN];
#pragma unroll
    for (int c = 0; c < NN; c++)
        w[c] = g_WT[c * HID + t];
    const float bh = b[t];

    // Phase A: 36 bins x 2 words (4 rows each) = 72 tasks; 16 independent
    // u32 loads per task (high MLP), packed-u16 accumulation (max 960).
    if (t < NN * 2) {
        const int c    = t >> 1;
        const int half = t & 1;           // rows half*4 .. half*4+3
        const unsigned* gp = g8 + c * HB4 + (i0 >> 2) + half;
        unsigned a01 = 0u, a23 = 0u;
#pragma unroll
        for (int sl = 0; sl < NSL; sl++) {
            const unsigned v = gp[sl * NN * HB4];
            a01 += __byte_perm(v, 0, 0x4140);   // (b0,b1) as u16 pair
            a23 += __byte_perm(v, 0, 0x4342);   // (b2,b3)
        }
        const unsigned self = (c == 3 * GN + 3) ? 1u : 0u;
        const int r0 = half * 4;
        cs[r0 + 0][c] = (float)((a01 & 0xFFFFu) - self);
        cs[r0 + 1][c] = (float)((a01 >> 16)     - self);
        cs[r0 + 2][c] = (float)((a23 & 0xFFFFu) - self);
        cs[r0 + 3][c] = (float)((a23 >> 16)     - self);
    }
    __syncthreads();

    // Phase B: 8 rows x 36 FMAs; cs reads are warp-uniform broadcasts.
#pragma unroll
    for (int r = 0; r < 8; r++) {
        float acc = bh;
#pragma unroll
        for (int c = 0; c < NN; c++)
            acc = fmaf(cs[r][c], w[c], acc);
        out[(i0 + r) * HID + t] = acc;     // coalesced STG.32
    }
}

// ---------------------------------------------------------------------------
// Inputs: 0 hidden_state (unused), 1 obs1 (unused), 2 obs2 [8192,2],
// 3 W [128,36], 4 b [128]. Output fp32 [8192,128].
// ---------------------------------------------------------------------------
extern "C" void kernel_launch(void* const* d_in, const int* in_sizes, int n_in,
                              void* d_out, int out_size) {
    const float* obs2 = (const float*)d_in[2];
    const float* W    = (const float*)d_in[3];
    const float* b    = (const float*)d_in[4];
    float*       out  = (float*)d_out;

    dim3 g1(NPED / RPB, NSL);        // 64 x 16 = 1024 blocks
    count_kernel<<<g1, RPB>>>(obs2, W);
    embed_kernel<<<NPED / 8, HID>>>(b, out);
}